// round 2
// baseline (speedup 1.0000x reference)
#include <cuda_runtime.h>
#include <cstdint>

#define B_    64
#define V_    2048
#define ENC_  128
#define T_    100
#define EMB_  256
#define DEC_  512
#define ATT_  256
#define VOC_  29
#define XDIM_ 896   // EMB + ENC + DEC (x concat + h for the fused gates GEMM)

// ---------------- scratch (static device globals; no allocation) ----------------
__device__ float g_enc_att[(size_t)B_ * V_ * ATT_];   // 134 MB
__device__ float g_mean[B_ * ENC_];
__device__ float g_h[B_ * DEC_];
__device__ float g_c[B_ * DEC_];
__device__ float g_dec_att[B_ * ATT_];
__device__ float g_gate[B_ * ENC_];
__device__ float g_scores[B_ * V_];
__device__ float g_x[B_ * XDIM_];                      // [emb(256) | gated awe(128) | h(512)]
__device__ float g_gates[B_ * 4 * DEC_];

__device__ __forceinline__ float sigm(float x) { return 1.0f / (1.0f + __expf(-x)); }

// ---------------- enc_att = encoder_output @ W_enc^T + b_enc ----------------
// grid: (B*V)/16 CTAs, 256 threads. W_enc^T staged in (padded) smem.
__global__ void k_enc_att(const float* __restrict__ enc,
                          const float* __restrict__ W_enc,
                          const float* __restrict__ b_enc) {
    extern __shared__ float sm[];
    float* sWT = sm;                 // [128][257] padded
    float* sE  = sm + 128 * 257;     // [16][128]
    int tid = threadIdx.x;
    for (int idx = tid; idx < ATT_ * ENC_; idx += 256) {
        int a = idx >> 7, e = idx & 127;
        sWT[e * 257 + a] = W_enc[idx];
    }
    int row0 = blockIdx.x * 16;
    for (int idx = tid; idx < 16 * ENC_; idx += 256) {
        int r = idx >> 7, e = idx & 127;
        sE[r * ENC_ + e] = enc[(size_t)(row0 + r) * ENC_ + e];
    }
    __syncthreads();
    int a = tid;
    float bb = b_enc[a];
    float acc[16];
#pragma unroll
    for (int r = 0; r < 16; r++) acc[r] = bb;
    for (int e = 0; e < ENC_; e++) {
        float w = sWT[e * 257 + a];
#pragma unroll
        for (int r = 0; r < 16; r++) acc[r] = fmaf(sE[r * ENC_ + e], w, acc[r]);
    }
#pragma unroll
    for (int r = 0; r < 16; r++)
        g_enc_att[(size_t)(row0 + r) * ATT_ + a] = acc[r];
}

// ---------------- mean over V ----------------
__global__ void k_mean(const float* __restrict__ enc) {
    int b = blockIdx.x, tid = threadIdx.x;
    int g = tid >> 7, e = tid & 127;
    const float* base = enc + ((size_t)b * V_ + g * 512) * ENC_ + e;
    float s = 0.f;
#pragma unroll 8
    for (int v = 0; v < 512; v++) s += base[(size_t)v * ENC_];
    __shared__ float sp[4][128];
    sp[g][e] = s;
    __syncthreads();
    if (tid < 128)
        g_mean[b * ENC_ + tid] = (sp[0][tid] + sp[1][tid] + sp[2][tid] + sp[3][tid]) * (1.0f / V_);
}

// dec_att + gate from h held in smem (shared by init and cell)
__device__ __forceinline__ void attention_pre(int b, int tid, const float* sh,
                                              const float* __restrict__ W_dec,
                                              const float* __restrict__ b_dec,
                                              const float* __restrict__ W_beta,
                                              const float* __restrict__ b_beta) {
    const float4* h4 = (const float4*)sh;
    if (tid < ATT_) {
        float acc = b_dec[tid];
        const float4* w = (const float4*)(W_dec + tid * DEC_);
#pragma unroll 8
        for (int k = 0; k < DEC_ / 4; k++) {
            float4 a = w[k]; float4 h = h4[k];
            acc += a.x * h.x + a.y * h.y + a.z * h.z + a.w * h.w;
        }
        g_dec_att[b * ATT_ + tid] = acc;
    } else if (tid < ATT_ + ENC_) {
        int e = tid - ATT_;
        float acc = b_beta[e];
        const float4* w = (const float4*)(W_beta + e * DEC_);
#pragma unroll 8
        for (int k = 0; k < DEC_ / 4; k++) {
            float4 a = w[k]; float4 h = h4[k];
            acc += a.x * h.x + a.y * h.y + a.z * h.z + a.w * h.w;
        }
        g_gate[b * ENC_ + e] = sigm(acc);
    }
}

// ---------------- h0/c0 + first dec_att/gate ----------------
__global__ void k_init(const float* __restrict__ Wh, const float* __restrict__ bh,
                       const float* __restrict__ Wc, const float* __restrict__ bc,
                       const float* __restrict__ W_dec, const float* __restrict__ b_dec,
                       const float* __restrict__ W_beta, const float* __restrict__ b_beta) {
    int b = blockIdx.x, tid = threadIdx.x;
    __shared__ float smn[ENC_];
    __shared__ float sh[DEC_];
    if (tid < ENC_) smn[tid] = g_mean[b * ENC_ + tid];
    __syncthreads();
    {
        int d = tid;
        float ah = bh[d], ac = bc[d];
        const float4* wrh = (const float4*)(Wh + d * ENC_);
        const float4* wrc = (const float4*)(Wc + d * ENC_);
        const float4* mv  = (const float4*)smn;
#pragma unroll 8
        for (int k = 0; k < ENC_ / 4; k++) {
            float4 m4 = mv[k]; float4 h4 = wrh[k]; float4 c4 = wrc[k];
            ah += m4.x * h4.x + m4.y * h4.y + m4.z * h4.z + m4.w * h4.w;
            ac += m4.x * c4.x + m4.y * c4.y + m4.z * c4.z + m4.w * c4.w;
        }
        g_h[b * DEC_ + d] = ah;
        g_c[b * DEC_ + d] = ac;
        g_x[b * XDIM_ + EMB_ + ENC_ + d] = ah;   // h slice of x-vector
        sh[d] = ah;
    }
    __syncthreads();
    attention_pre(b, tid, sh, W_dec, b_dec, W_beta, b_beta);
}

// ---------------- scores = relu(enc_att + dec_att) @ w_full + b_full ----------------
// grid 4096 = 64 b * 64 vblocks(32 v); block 256 = 8 warps; warp handles 4 v.
__global__ void k_scores(const float* __restrict__ w_full, const float* __restrict__ b_full) {
    int b = blockIdx.x >> 6;
    int v0 = (blockIdx.x & 63) * 32;
    __shared__ float sda[ATT_], sw[ATT_];
    int tid = threadIdx.x;
    sda[tid] = g_dec_att[b * ATT_ + tid];
    sw[tid]  = w_full[tid];
    __syncthreads();
    int warp = tid >> 5, lane = tid & 31;
    float bf = b_full[0];
#pragma unroll
    for (int i = 0; i < 4; i++) {
        int v = v0 + warp * 4 + i;
        const float* row = g_enc_att + (size_t)(b * V_ + v) * ATT_;
        float acc = 0.f;
#pragma unroll
        for (int k = 0; k < 8; k++) {
            int a = lane + k * 32;
            acc += fmaxf(row[a] + sda[a], 0.f) * sw[a];
        }
#pragma unroll
        for (int o = 16; o; o >>= 1) acc += __shfl_xor_sync(0xFFFFFFFFu, acc, o);
        if (lane == 0) g_scores[b * V_ + v] = acc + bf;
    }
}

// ---------------- softmax + alpha-out + awe + x build ----------------
__global__ void k_smax_awe(const float* __restrict__ enc, const int* __restrict__ caps,
                           const int* __restrict__ lens, const float* __restrict__ emb_W,
                           float* __restrict__ out_alpha, int t) {
    int b = blockIdx.x, tid = threadIdx.x;
    __shared__ float s_alpha[V_];
    __shared__ float red[16];
    __shared__ float part[4][128];

    float sc[4];
#pragma unroll
    for (int i = 0; i < 4; i++) sc[i] = g_scores[b * V_ + tid + i * 512];
    float mx = fmaxf(fmaxf(sc[0], sc[1]), fmaxf(sc[2], sc[3]));
#pragma unroll
    for (int o = 16; o; o >>= 1) mx = fmaxf(mx, __shfl_xor_sync(0xFFFFFFFFu, mx, o));
    if ((tid & 31) == 0) red[tid >> 5] = mx;
    __syncthreads();
    if (tid == 0) {
        float m = red[0];
#pragma unroll
        for (int i = 1; i < 16; i++) m = fmaxf(m, red[i]);
        red[0] = m;
    }
    __syncthreads();
    mx = red[0];
    float se = 0.f;
#pragma unroll
    for (int i = 0; i < 4; i++) { sc[i] = __expf(sc[i] - mx); se += sc[i]; }
#pragma unroll
    for (int o = 16; o; o >>= 1) se += __shfl_xor_sync(0xFFFFFFFFu, se, o);
    __syncthreads();
    if ((tid & 31) == 0) red[tid >> 5] = se;
    __syncthreads();
    if (tid == 0) {
        float s = 0.f;
#pragma unroll
        for (int i = 0; i < 16; i++) s += red[i];
        red[0] = s;
    }
    __syncthreads();
    float inv = 1.0f / red[0];
    bool m = t < lens[b];
    float* oa = out_alpha + (size_t)(b * T_ + t) * V_;
#pragma unroll
    for (int i = 0; i < 4; i++) {
        float al = sc[i] * inv;
        s_alpha[tid + i * 512] = al;
        oa[tid + i * 512] = m ? al : 0.f;
    }
    __syncthreads();

    // awe = sum_v alpha[v] * enc[b,v,:]
    int g = tid >> 7, e = tid & 127;
    const float* base = enc + ((size_t)b * V_ + g * 512) * ENC_ + e;
    const float* ap = s_alpha + g * 512;
    float s = 0.f;
#pragma unroll 8
    for (int v = 0; v < 512; v++) s += ap[v] * base[(size_t)v * ENC_];
    part[g][e] = s;
    __syncthreads();
    if (tid < 128) {
        float awe = (part[0][tid] + part[1][tid] + part[2][tid] + part[3][tid]) * g_gate[b * ENC_ + tid];
        g_x[b * XDIM_ + EMB_ + tid] = awe;
    }
    if (tid < 256) {
        int cap = caps[b * T_ + t];
        g_x[b * XDIM_ + tid] = emb_W[cap * EMB_ + tid];
    }
}

// ---------------- gates GEMM: [64 x 896] @ [896 x 2048] ----------------
// grid 128 (16 j per CTA), block 256, 4 b-rows per thread.
__global__ void k_gemm(const float* __restrict__ W_ih, const float* __restrict__ W_hh,
                       const float* __restrict__ b_ih, const float* __restrict__ b_hh) {
    int j0 = blockIdx.x * 16;
    __shared__ float sX[64 * 33];
    __shared__ float sW[32 * 16];
    int tid = threadIdx.x;
    int jj = tid & 15, bq = tid >> 4;
    float acc[4] = {0.f, 0.f, 0.f, 0.f};
    for (int kc = 0; kc < 28; kc++) {
        int k0 = kc * 32;
#pragma unroll
        for (int r = 0; r < 8; r++) {
            int idx = tid + r * 256;
            int bb = idx >> 5, kk = idx & 31;
            sX[bb * 33 + kk] = g_x[bb * XDIM_ + k0 + kk];
        }
        const float* src; int ld, koff;
        if (k0 < 384) { src = W_ih; ld = 384; koff = k0; }
        else          { src = W_hh; ld = DEC_; koff = k0 - 384; }
#pragma unroll
        for (int r = 0; r < 2; r++) {
            int e = tid + r * 256;
            int j2 = e >> 5, kk = e & 31;
            sW[kk * 16 + j2] = src[(j0 + j2) * ld + koff + kk];
        }
        __syncthreads();
#pragma unroll
        for (int kk = 0; kk < 32; kk++) {
            float w = sW[kk * 16 + jj];
#pragma unroll
            for (int i = 0; i < 4; i++)
                acc[i] = fmaf(sX[(bq * 4 + i) * 33 + kk], w, acc[i]);
        }
        __syncthreads();
    }
    int j = j0 + jj;
    float bias = b_ih[j] + b_hh[j];
#pragma unroll
    for (int i = 0; i < 4; i++)
        g_gates[(bq * 4 + i) * (4 * DEC_) + j] = acc[i] + bias;
}

// ---------------- LSTM cell + pred + next dec_att/gate ----------------
__global__ void k_cell(const int* __restrict__ lens,
                       const float* __restrict__ W_final, const float* __restrict__ b_final,
                       const float* __restrict__ W_dec, const float* __restrict__ b_dec,
                       const float* __restrict__ W_beta, const float* __restrict__ b_beta,
                       float* __restrict__ out_pred, int t) {
    int b = blockIdx.x, tid = threadIdx.x;
    __shared__ float shn[DEC_];
    __shared__ float sh2[DEC_];
    int base = b * 4 * DEC_;
    float ig = sigm(g_gates[base + tid]);
    float fg = sigm(g_gates[base + DEC_ + tid]);
    float gg = tanhf(g_gates[base + 2 * DEC_ + tid]);
    float og = sigm(g_gates[base + 3 * DEC_ + tid]);
    float c_old = g_c[b * DEC_ + tid];
    float cn = fg * c_old + ig * gg;
    float hn = og * tanhf(cn);
    bool m = t < lens[b];
    float h_old = g_h[b * DEC_ + tid];
    float h2 = m ? hn : h_old;
    float c2 = m ? cn : c_old;
    g_h[b * DEC_ + tid] = h2;
    g_c[b * DEC_ + tid] = c2;
    g_x[b * XDIM_ + EMB_ + ENC_ + tid] = h2;
    shn[tid] = hn;
    sh2[tid] = h2;
    __syncthreads();
    int warp = tid >> 5, lane = tid & 31;
#pragma unroll
    for (int pp = 0; pp < 2; pp++) {
        int p = warp + pp * 16;
        if (p < VOC_) {
            float acc = 0.f;
#pragma unroll
            for (int k = 0; k < 16; k++)
                acc += shn[lane + 32 * k] * W_final[p * DEC_ + lane + 32 * k];
#pragma unroll
            for (int o = 16; o; o >>= 1) acc += __shfl_xor_sync(0xFFFFFFFFu, acc, o);
            if (lane == 0)
                out_pred[(size_t)(b * T_ + t) * VOC_ + p] = m ? (acc + b_final[p]) : 0.f;
        }
    }
    attention_pre(b, tid, sh2, W_dec, b_dec, W_beta, b_beta);
}

__global__ void k_lens(const int* __restrict__ lens, float* __restrict__ out) {
    int i = threadIdx.x;
    if (i < B_) out[i] = (float)lens[i];
}

// ---------------- launch ----------------
extern "C" void kernel_launch(void* const* d_in, const int* in_sizes, int n_in,
                              void* d_out, int out_size) {
    const float* enc      = (const float*)d_in[0];
    const int*   caps     = (const int*)  d_in[1];
    const int*   lens     = (const int*)  d_in[2];
    const float* emb_W    = (const float*)d_in[3];
    const float* W_enc    = (const float*)d_in[4];
    const float* b_enc    = (const float*)d_in[5];
    const float* W_dec    = (const float*)d_in[6];
    const float* b_dec    = (const float*)d_in[7];
    const float* w_full   = (const float*)d_in[8];
    const float* b_full   = (const float*)d_in[9];
    const float* W_ih     = (const float*)d_in[10];
    const float* b_ih     = (const float*)d_in[11];
    const float* W_hh     = (const float*)d_in[12];
    const float* b_hh     = (const float*)d_in[13];
    const float* W_init_h = (const float*)d_in[14];
    const float* b_init_h = (const float*)d_in[15];
    const float* W_init_c = (const float*)d_in[16];
    const float* b_init_c = (const float*)d_in[17];
    const float* W_beta   = (const float*)d_in[18];
    const float* b_beta   = (const float*)d_in[19];
    const float* W_final  = (const float*)d_in[20];
    const float* b_final  = (const float*)d_in[21];

    float* out       = (float*)d_out;
    float* out_pred  = out;                                    // [B,T,VOC]
    float* out_alpha = out + (size_t)B_ * T_ * VOC_;           // [B,T,V]
    float* out_lens  = out_alpha + (size_t)B_ * T_ * V_;       // [B]

    const int SMEM_EA = (128 * 257 + 16 * 128) * 4;            // 139776 B
    static bool attr_done = false;
    if (!attr_done) {
        cudaFuncSetAttribute(k_enc_att, cudaFuncAttributeMaxDynamicSharedMemorySize, SMEM_EA);
        attr_done = true;
    }

    k_enc_att<<<(B_ * V_) / 16, 256, SMEM_EA>>>(enc, W_enc, b_enc);
    k_mean<<<B_, 512>>>(enc);
    k_init<<<B_, 512>>>(W_init_h, b_init_h, W_init_c, b_init_c,
                        W_dec, b_dec, W_beta, b_beta);
    for (int t = 0; t < T_; t++) {
        k_scores<<<4096, 256>>>(w_full, b_full);
        k_smax_awe<<<B_, 512>>>(enc, caps, lens, emb_W, out_alpha, t);
        k_gemm<<<128, 256>>>(W_ih, W_hh, b_ih, b_hh);
        k_cell<<<B_, 512>>>(lens, W_final, b_final, W_dec, b_dec, W_beta, b_beta,
                            out_pred, t);
    }
    k_lens<<<1, 64>>>(lens, out_lens);
}

// round 3
// speedup vs baseline: 1.3370x; 1.3370x over previous
#include <cuda_runtime.h>
#include <cuda_bf16.h>
#include <cstdint>

#define B_    64
#define V_    2048
#define ENC_  128
#define T_    100
#define EMB_  256
#define DEC_  512
#define ATT_  256
#define VOC_  29
#define XDIM_ 896   // EMB + ENC + DEC

// ---------------- scratch ----------------
__device__ __nv_bfloat16 g_enc_att_bf[(size_t)B_ * V_ * ATT_];   // 67 MB
__device__ __nv_bfloat16 g_enc_bf[(size_t)B_ * V_ * ENC_];       // 33.5 MB
__device__ float g_mean[B_ * ENC_];
__device__ float g_h[B_ * DEC_];
__device__ float g_c[B_ * DEC_];
__device__ float g_dec_att[B_ * ATT_];
__device__ float g_gate[B_ * ENC_];
__device__ float g_scores[B_ * V_];
__device__ float g_x[B_ * XDIM_];                      // [emb(256) | gated awe(128) | h(512)]
__device__ float g_gates_p[2][B_ * 4 * DEC_];          // split-K partials

__device__ __forceinline__ float sigm(float x) { return 1.0f / (1.0f + __expf(-x)); }

// ---------------- enc -> bf16 copy (once) ----------------
__global__ void k_enc_bf(const float* __restrict__ enc) {
    size_t i = (size_t)blockIdx.x * blockDim.x + threadIdx.x;   // over 16.7M/4
    const float4* in = (const float4*)enc;
    float4 v = in[i];
    __nv_bfloat162* out = (__nv_bfloat162*)g_enc_bf;
    out[i * 2]     = __floats2bfloat162_rn(v.x, v.y);
    out[i * 2 + 1] = __floats2bfloat162_rn(v.z, v.w);
}

// ---------------- enc_att = enc @ W_enc^T + b_enc  (bf16 out, once) ----------------
__global__ void k_enc_att(const float* __restrict__ enc,
                          const float* __restrict__ W_enc,
                          const float* __restrict__ b_enc) {
    extern __shared__ float sm[];
    float* sWT = sm;                 // [128][257]
    float* sE  = sm + 128 * 257;     // [16][128]
    int tid = threadIdx.x;
    for (int idx = tid; idx < ATT_ * ENC_; idx += 256) {
        int a = idx >> 7, e = idx & 127;
        sWT[e * 257 + a] = W_enc[idx];
    }
    int row0 = blockIdx.x * 16;
    for (int idx = tid; idx < 16 * ENC_; idx += 256) {
        int r = idx >> 7, e = idx & 127;
        sE[r * ENC_ + e] = enc[(size_t)(row0 + r) * ENC_ + e];
    }
    __syncthreads();
    int a = tid;
    float bb = b_enc[a];
    float acc[16];
#pragma unroll
    for (int r = 0; r < 16; r++) acc[r] = bb;
    for (int e = 0; e < ENC_; e++) {
        float w = sWT[e * 257 + a];
#pragma unroll
        for (int r = 0; r < 16; r++) acc[r] = fmaf(sE[r * ENC_ + e], w, acc[r]);
    }
#pragma unroll
    for (int r = 0; r < 16; r++)
        g_enc_att_bf[(size_t)(row0 + r) * ATT_ + a] = __float2bfloat16(acc[r]);
}

// ---------------- mean over V (once) ----------------
__global__ void k_mean(const float* __restrict__ enc) {
    int b = blockIdx.x, tid = threadIdx.x;
    int g = tid >> 7, e = tid & 127;
    const float* base = enc + ((size_t)b * V_ + g * 512) * ENC_ + e;
    float s = 0.f;
#pragma unroll 8
    for (int v = 0; v < 512; v++) s += base[(size_t)v * ENC_];
    __shared__ float sp[4][128];
    sp[g][e] = s;
    __syncthreads();
    if (tid < 128)
        g_mean[b * ENC_ + tid] = (sp[0][tid] + sp[1][tid] + sp[2][tid] + sp[3][tid]) * (1.0f / V_);
}

// dec_att + gate from h in smem
__device__ __forceinline__ void attention_pre(int b, int tid, const float* sh,
                                              const float* __restrict__ W_dec,
                                              const float* __restrict__ b_dec,
                                              const float* __restrict__ W_beta,
                                              const float* __restrict__ b_beta) {
    const float4* h4 = (const float4*)sh;
    if (tid < ATT_) {
        float acc = b_dec[tid];
        const float4* w = (const float4*)(W_dec + tid * DEC_);
#pragma unroll 8
        for (int k = 0; k < DEC_ / 4; k++) {
            float4 a = w[k]; float4 h = h4[k];
            acc += a.x * h.x + a.y * h.y + a.z * h.z + a.w * h.w;
        }
        g_dec_att[b * ATT_ + tid] = acc;
    } else if (tid < ATT_ + ENC_) {
        int e = tid - ATT_;
        float acc = b_beta[e];
        const float4* w = (const float4*)(W_beta + e * DEC_);
#pragma unroll 8
        for (int k = 0; k < DEC_ / 4; k++) {
            float4 a = w[k]; float4 h = h4[k];
            acc += a.x * h.x + a.y * h.y + a.z * h.z + a.w * h.w;
        }
        g_gate[b * ENC_ + e] = sigm(acc);
    }
}

// ---------------- h0/c0 + first dec_att/gate ----------------
__global__ void k_init(const float* __restrict__ Wh, const float* __restrict__ bh,
                       const float* __restrict__ Wc, const float* __restrict__ bc,
                       const float* __restrict__ W_dec, const float* __restrict__ b_dec,
                       const float* __restrict__ W_beta, const float* __restrict__ b_beta) {
    int b = blockIdx.x, tid = threadIdx.x;
    __shared__ float smn[ENC_];
    __shared__ float sh[DEC_];
    if (tid < ENC_) smn[tid] = g_mean[b * ENC_ + tid];
    __syncthreads();
    {
        int d = tid;
        float ah = bh[d], ac = bc[d];
        const float4* wrh = (const float4*)(Wh + d * ENC_);
        const float4* wrc = (const float4*)(Wc + d * ENC_);
        const float4* mv  = (const float4*)smn;
#pragma unroll 8
        for (int k = 0; k < ENC_ / 4; k++) {
            float4 m4 = mv[k]; float4 h4 = wrh[k]; float4 c4 = wrc[k];
            ah += m4.x * h4.x + m4.y * h4.y + m4.z * h4.z + m4.w * h4.w;
            ac += m4.x * c4.x + m4.y * c4.y + m4.z * c4.z + m4.w * c4.w;
        }
        g_h[b * DEC_ + d] = ah;
        g_c[b * DEC_ + d] = ac;
        g_x[b * XDIM_ + EMB_ + ENC_ + d] = ah;
        sh[d] = ah;
    }
    __syncthreads();
    attention_pre(b, tid, sh, W_dec, b_dec, W_beta, b_beta);
}

// ---------------- scores = relu(enc_att + dec_att) @ w_full + b_full ----------------
// bf16 enc_att; grid 4096, 256 thr, warp handles 4 v rows.
__global__ void k_scores(const float* __restrict__ w_full, const float* __restrict__ b_full) {
    int b = blockIdx.x >> 6;
    int v0 = (blockIdx.x & 63) * 32;
    __shared__ float sda[ATT_], sw[ATT_];
    int tid = threadIdx.x;
    sda[tid] = g_dec_att[b * ATT_ + tid];
    sw[tid]  = w_full[tid];
    __syncthreads();
    int warp = tid >> 5, lane = tid & 31;
    float bf = b_full[0];
#pragma unroll
    for (int i = 0; i < 4; i++) {
        int v = v0 + warp * 4 + i;
        const __nv_bfloat162* row =
            (const __nv_bfloat162*)(g_enc_att_bf + (size_t)(b * V_ + v) * ATT_);
        float acc = 0.f;
#pragma unroll
        for (int k = 0; k < 4; k++) {
            int a2 = lane + k * 32;
            float2 e2 = __bfloat1622float2(row[a2]);
            int a = a2 * 2;
            acc += fmaxf(e2.x + sda[a], 0.f) * sw[a]
                 + fmaxf(e2.y + sda[a + 1], 0.f) * sw[a + 1];
        }
#pragma unroll
        for (int o = 16; o; o >>= 1) acc += __shfl_xor_sync(0xFFFFFFFFu, acc, o);
        if (lane == 0) g_scores[b * V_ + v] = acc + bf;
    }
}

// ---------------- softmax + alpha-out + awe (bf16 enc) + x build ----------------
__global__ void k_smax_awe(const int* __restrict__ caps,
                           const int* __restrict__ lens, const float* __restrict__ emb_W,
                           float* __restrict__ out_alpha, int t) {
    int b = blockIdx.x, tid = threadIdx.x;   // 1024 threads
    __shared__ float s_alpha[V_];
    __shared__ float red[32];
    __shared__ float part[8][128];

    float sc[2];
    sc[0] = g_scores[b * V_ + tid];
    sc[1] = g_scores[b * V_ + tid + 1024];
    float mx = fmaxf(sc[0], sc[1]);
#pragma unroll
    for (int o = 16; o; o >>= 1) mx = fmaxf(mx, __shfl_xor_sync(0xFFFFFFFFu, mx, o));
    if ((tid & 31) == 0) red[tid >> 5] = mx;
    __syncthreads();
    if (tid == 0) {
        float m = red[0];
#pragma unroll
        for (int i = 1; i < 32; i++) m = fmaxf(m, red[i]);
        red[0] = m;
    }
    __syncthreads();
    mx = red[0];
    float se = 0.f;
#pragma unroll
    for (int i = 0; i < 2; i++) { sc[i] = __expf(sc[i] - mx); se += sc[i]; }
#pragma unroll
    for (int o = 16; o; o >>= 1) se += __shfl_xor_sync(0xFFFFFFFFu, se, o);
    __syncthreads();
    if ((tid & 31) == 0) red[tid >> 5] = se;
    __syncthreads();
    if (tid == 0) {
        float s = 0.f;
#pragma unroll
        for (int i = 0; i < 32; i++) s += red[i];
        red[0] = s;
    }
    __syncthreads();
    float inv = 1.0f / red[0];
    bool m = t < lens[b];
    float* oa = out_alpha + (size_t)(b * T_ + t) * V_;
    {
        float a0 = sc[0] * inv, a1 = sc[1] * inv;
        s_alpha[tid] = a0;          oa[tid] = m ? a0 : 0.f;
        s_alpha[tid + 1024] = a1;   oa[tid + 1024] = m ? a1 : 0.f;
    }
    __syncthreads();

    // awe = sum_v alpha[v] * enc_bf[b,v,:]; 8 groups of 256 v
    int g = tid >> 7, e = tid & 127;
    const __nv_bfloat16* base = g_enc_bf + ((size_t)b * V_ + g * 256) * ENC_ + e;
    const float* ap = s_alpha + g * 256;
    float s = 0.f;
#pragma unroll 8
    for (int v = 0; v < 256; v++) s += ap[v] * __bfloat162float(base[(size_t)v * ENC_]);
    part[g][e] = s;
    __syncthreads();
    if (tid < 128) {
        float awe = (part[0][tid] + part[1][tid] + part[2][tid] + part[3][tid]
                   + part[4][tid] + part[5][tid] + part[6][tid] + part[7][tid])
                  * g_gate[b * ENC_ + tid];
        g_x[b * XDIM_ + EMB_ + tid] = awe;
    }
    if (tid < 256) {
        int cap = caps[b * T_ + t];
        g_x[b * XDIM_ + tid] = emb_W[cap * EMB_ + tid];
    }
}

// ---------------- split-K gates GEMM ----------------
// grid (128,2): y=0 -> X[:,0:384]@W_ih^T, y=1 -> X[:,384:896]@W_hh^T.
__global__ void k_gemm(const float* __restrict__ W_ih, const float* __restrict__ W_hh) {
    int slab = blockIdx.y;
    int j0 = blockIdx.x * 16;
    __shared__ float sX[64 * 33];
    __shared__ float sW[32 * 16];
    int tid = threadIdx.x;
    int jj = tid & 15, bq = tid >> 4;
    const float* src = slab ? W_hh : W_ih;
    int ld   = slab ? DEC_ : 384;
    int kx0  = slab ? 384 : 0;
    int nch  = slab ? 16 : 12;
    float acc[4] = {0.f, 0.f, 0.f, 0.f};
    for (int kc = 0; kc < nch; kc++) {
        int k0 = kc * 32;
#pragma unroll
        for (int r = 0; r < 8; r++) {
            int idx = tid + r * 256;
            int bb = idx >> 5, kk = idx & 31;
            sX[bb * 33 + kk] = g_x[bb * XDIM_ + kx0 + k0 + kk];
        }
#pragma unroll
        for (int r = 0; r < 2; r++) {
            int e = tid + r * 256;
            int j2 = e >> 5, kk = e & 31;
            sW[kk * 16 + j2] = src[(j0 + j2) * ld + k0 + kk];
        }
        __syncthreads();
#pragma unroll
        for (int kk = 0; kk < 32; kk++) {
            float w = sW[kk * 16 + jj];
#pragma unroll
            for (int i = 0; i < 4; i++)
                acc[i] = fmaf(sX[(bq * 4 + i) * 33 + kk], w, acc[i]);
        }
        __syncthreads();
    }
    int j = j0 + jj;
#pragma unroll
    for (int i = 0; i < 4; i++)
        g_gates_p[slab][(bq * 4 + i) * (4 * DEC_) + j] = acc[i];
}

// ---------------- LSTM cell + pred + next dec_att/gate ----------------
__global__ void k_cell(const int* __restrict__ lens,
                       const float* __restrict__ b_ih, const float* __restrict__ b_hh,
                       const float* __restrict__ W_final, const float* __restrict__ b_final,
                       const float* __restrict__ W_dec, const float* __restrict__ b_dec,
                       const float* __restrict__ W_beta, const float* __restrict__ b_beta,
                       float* __restrict__ out_pred, int t) {
    int b = blockIdx.x, tid = threadIdx.x;
    __shared__ float shn[DEC_];
    __shared__ float sh2[DEC_];
    int base = b * 4 * DEC_;
    float gi = g_gates_p[0][base + tid]            + g_gates_p[1][base + tid]
             + b_ih[tid]            + b_hh[tid];
    float gf = g_gates_p[0][base + DEC_ + tid]     + g_gates_p[1][base + DEC_ + tid]
             + b_ih[DEC_ + tid]     + b_hh[DEC_ + tid];
    float gg = g_gates_p[0][base + 2 * DEC_ + tid] + g_gates_p[1][base + 2 * DEC_ + tid]
             + b_ih[2 * DEC_ + tid] + b_hh[2 * DEC_ + tid];
    float go = g_gates_p[0][base + 3 * DEC_ + tid] + g_gates_p[1][base + 3 * DEC_ + tid]
             + b_ih[3 * DEC_ + tid] + b_hh[3 * DEC_ + tid];
    float ig = sigm(gi), fg = sigm(gf), og = sigm(go);
    float gt = tanhf(gg);
    float c_old = g_c[b * DEC_ + tid];
    float cn = fg * c_old + ig * gt;
    float hn = og * tanhf(cn);
    bool m = t < lens[b];
    float h_old = g_h[b * DEC_ + tid];
    float h2 = m ? hn : h_old;
    float c2 = m ? cn : c_old;
    g_h[b * DEC_ + tid] = h2;
    g_c[b * DEC_ + tid] = c2;
    g_x[b * XDIM_ + EMB_ + ENC_ + tid] = h2;
    shn[tid] = hn;
    sh2[tid] = h2;
    __syncthreads();
    int warp = tid >> 5, lane = tid & 31;
#pragma unroll
    for (int pp = 0; pp < 2; pp++) {
        int p = warp + pp * 16;
        if (p < VOC_) {
            float acc = 0.f;
#pragma unroll
            for (int k = 0; k < 16; k++)
                acc += shn[lane + 32 * k] * W_final[p * DEC_ + lane + 32 * k];
#pragma unroll
            for (int o = 16; o; o >>= 1) acc += __shfl_xor_sync(0xFFFFFFFFu, acc, o);
            if (lane == 0)
                out_pred[(size_t)(b * T_ + t) * VOC_ + p] = m ? (acc + b_final[p]) : 0.f;
        }
    }
    attention_pre(b, tid, sh2, W_dec, b_dec, W_beta, b_beta);
}

__global__ void k_lens(const int* __restrict__ lens, float* __restrict__ out) {
    int i = threadIdx.x;
    if (i < B_) out[i] = (float)lens[i];
}

// ---------------- launch ----------------
extern "C" void kernel_launch(void* const* d_in, const int* in_sizes, int n_in,
                              void* d_out, int out_size) {
    const float* enc      = (const float*)d_in[0];
    const int*   caps     = (const int*)  d_in[1];
    const int*   lens     = (const int*)  d_in[2];
    const float* emb_W    = (const float*)d_in[3];
    const float* W_enc    = (const float*)d_in[4];
    const float* b_enc    = (const float*)d_in[5];
    const float* W_dec    = (const float*)d_in[6];
    const float* b_dec    = (const float*)d_in[7];
    const float* w_full   = (const float*)d_in[8];
    const float* b_full   = (const float*)d_in[9];
    const float* W_ih     = (const float*)d_in[10];
    const float* b_ih     = (const float*)d_in[11];
    const float* W_hh     = (const float*)d_in[12];
    const float* b_hh     = (const float*)d_in[13];
    const float* W_init_h = (const float*)d_in[14];
    const float* b_init_h = (const float*)d_in[15];
    const float* W_init_c = (const float*)d_in[16];
    const float* b_init_c = (const float*)d_in[17];
    const float* W_beta   = (const float*)d_in[18];
    const float* b_beta   = (const float*)d_in[19];
    const float* W_final  = (const float*)d_in[20];
    const float* b_final  = (const float*)d_in[21];

    float* out       = (float*)d_out;
    float* out_pred  = out;                                    // [B,T,VOC]
    float* out_alpha = out + (size_t)B_ * T_ * VOC_;           // [B,T,V]
    float* out_lens  = out_alpha + (size_t)B_ * T_ * V_;       // [B]

    const int SMEM_EA = (128 * 257 + 16 * 128) * 4;
    static bool attr_done = false;
    if (!attr_done) {
        cudaFuncSetAttribute(k_enc_att, cudaFuncAttributeMaxDynamicSharedMemorySize, SMEM_EA);
        attr_done = true;
    }

    k_enc_bf<<<(B_ * V_ * ENC_) / 4 / 256, 256>>>(enc);
    k_enc_att<<<(B_ * V_) / 16, 256, SMEM_EA>>>(enc, W_enc, b_enc);
    k_mean<<<B_, 512>>>(enc);
    k_init<<<B_, 512>>>(W_init_h, b_init_h, W_init_c, b_init_c,
                        W_dec, b_dec, W_beta, b_beta);
    for (int t = 0; t < T_; t++) {
        k_scores<<<4096, 256>>>(w_full, b_full);
        k_smax_awe<<<B_, 1024>>>(caps, lens, emb_W, out_alpha, t);
        dim3 gg(128, 2);
        k_gemm<<<gg, 256>>>(W_ih, W_hh);
        k_cell<<<B_, 512>>>(lens, b_ih, b_hh, W_final, b_final,
                            W_dec, b_dec, W_beta, b_beta, out_pred, t);
    }
    k_lens<<<1, 64>>>(lens, out_lens);
}